// round 5
// baseline (speedup 1.0000x reference)
#include <cuda_runtime.h>
#include <cuda_bf16.h>
#include <cstdint>

// HardBinaryVote: inputs [V=31, B=2,000,000] row-major, values in {0,1}
// (physically int32 OR float32 — for both, vote == (bit pattern != 0)).
// out[b] = argmax([count0, count1]) = (2 * popcount_of_ones > V).
// Output written as FLOAT32 0.0f / 1.0f (hypothesis: metadata __output__ is f32;
// all prior int32-written outputs read as denormals ~ 0 -> rel_err exactly 1.0).

static constexpr int THREADS = 256;

__global__ __launch_bounds__(THREADS)
void vote_vec4(const uint4* __restrict__ in4,
               float4* __restrict__ out4,
               int n4, int V) {
    int idx = blockIdx.x * THREADS + threadIdx.x;
    if (idx >= n4) return;

    int s0 = 0, s1 = 0, s2 = 0, s3 = 0;
#pragma unroll 31
    for (int v = 0; v < V; v++) {
        uint4 x = __ldg(&in4[(long long)v * n4 + idx]);
        s0 += (x.x != 0u);
        s1 += (x.y != 0u);
        s2 += (x.z != 0u);
        s3 += (x.w != 0u);
    }

    float4 o;
    o.x = (2 * s0 > V) ? 1.0f : 0.0f;
    o.y = (2 * s1 > V) ? 1.0f : 0.0f;
    o.z = (2 * s2 > V) ? 1.0f : 0.0f;
    o.w = (2 * s3 > V) ? 1.0f : 0.0f;
    out4[idx] = o;
}

// Scalar tail / fallback for B % 4 != 0 (column-indexed so row stride stays B).
__global__ __launch_bounds__(THREADS)
void vote_scalar(const unsigned int* __restrict__ in,
                 float* __restrict__ out,
                 int B, int V, int start) {
    int b = start + blockIdx.x * THREADS + threadIdx.x;
    if (b >= B) return;
    int s = 0;
    for (int v = 0; v < V; v++) s += (in[(long long)v * B + b] != 0u);
    out[b] = (2 * s > V) ? 1.0f : 0.0f;
}

extern "C" void kernel_launch(void* const* d_in, const int* in_sizes, int n_in,
                              void* d_out, int out_size) {
    const unsigned int* in = (const unsigned int*)d_in[0];
    float* out = (float*)d_out;

    const long long Sin = in_sizes[0];
    long long B = out_size;
    if (B <= 0) return;
    long long V = (Sin % B == 0) ? (Sin / B) : 31;
    if (V <= 0) V = 1;

    if (B % 4 == 0) {
        int n4 = (int)(B / 4);
        int blocks = (n4 + THREADS - 1) / THREADS;
        vote_vec4<<<blocks, THREADS>>>((const uint4*)in, (float4*)out,
                                       n4, (int)V);
    } else {
        int blocks = (int)((B + THREADS - 1) / THREADS);
        vote_scalar<<<blocks, THREADS>>>(in, out, (int)B, (int)V, 0);
    }
}

// round 6
// speedup vs baseline: 1.0051x; 1.0051x over previous
#include <cuda_runtime.h>
#include <cuda_bf16.h>
#include <cstdint>

// HardBinaryVote: inputs [V=31, B=2,000,000] row-major {0,1} (int32 or f32 —
// either way vote == (bits != 0)); out[b] (FLOAT32) = majority = (2*ones > V).
//
// R5: persistent grid-stride (148 SMs x 8 CTAs, single wave, per-SM-balanced
// DRAM stream), streaming loads/stores (.cs, data touched once), V=31 fully
// unrolled template.

static constexpr int THREADS = 256;
static constexpr int NSM = 148;
static constexpr int CTAS_PER_SM = 8;

template <int V>
__global__ __launch_bounds__(THREADS)
void vote_vec4_persist(const uint4* __restrict__ in4,
                       float4* __restrict__ out4,
                       int n4) {
    const int stride = gridDim.x * THREADS;
    for (int idx = blockIdx.x * THREADS + threadIdx.x; idx < n4; idx += stride) {
        int s0 = 0, s1 = 0, s2 = 0, s3 = 0;
#pragma unroll
        for (int v = 0; v < V; v++) {
            uint4 x = __ldcs(&in4[(long long)v * n4 + idx]);
            s0 += (x.x != 0u);
            s1 += (x.y != 0u);
            s2 += (x.z != 0u);
            s3 += (x.w != 0u);
        }
        float4 o;
        o.x = (2 * s0 > V) ? 1.0f : 0.0f;
        o.y = (2 * s1 > V) ? 1.0f : 0.0f;
        o.z = (2 * s2 > V) ? 1.0f : 0.0f;
        o.w = (2 * s3 > V) ? 1.0f : 0.0f;
        __stcs(&out4[idx], o);
    }
}

// Runtime-V fallback (same structure, inner loop not fully unrolled).
__global__ __launch_bounds__(THREADS)
void vote_vec4_dyn(const uint4* __restrict__ in4,
                   float4* __restrict__ out4,
                   int n4, int V) {
    const int stride = gridDim.x * THREADS;
    for (int idx = blockIdx.x * THREADS + threadIdx.x; idx < n4; idx += stride) {
        int s0 = 0, s1 = 0, s2 = 0, s3 = 0;
#pragma unroll 8
        for (int v = 0; v < V; v++) {
            uint4 x = __ldcs(&in4[(long long)v * n4 + idx]);
            s0 += (x.x != 0u);
            s1 += (x.y != 0u);
            s2 += (x.z != 0u);
            s3 += (x.w != 0u);
        }
        float4 o;
        o.x = (2 * s0 > V) ? 1.0f : 0.0f;
        o.y = (2 * s1 > V) ? 1.0f : 0.0f;
        o.z = (2 * s2 > V) ? 1.0f : 0.0f;
        o.w = (2 * s3 > V) ? 1.0f : 0.0f;
        __stcs(&out4[idx], o);
    }
}

// Scalar fallback for B % 4 != 0.
__global__ __launch_bounds__(THREADS)
void vote_scalar(const unsigned int* __restrict__ in,
                 float* __restrict__ out,
                 int B, int V) {
    int b = blockIdx.x * THREADS + threadIdx.x;
    const int stride = gridDim.x * THREADS;
    for (; b < B; b += stride) {
        int s = 0;
        for (int v = 0; v < V; v++) s += (in[(long long)v * B + b] != 0u);
        out[b] = (2 * s > V) ? 1.0f : 0.0f;
    }
}

extern "C" void kernel_launch(void* const* d_in, const int* in_sizes, int n_in,
                              void* d_out, int out_size) {
    const unsigned int* in = (const unsigned int*)d_in[0];
    float* out = (float*)d_out;

    const long long Sin = in_sizes[0];
    long long B = out_size;
    if (B <= 0) return;
    long long V = (Sin % B == 0) ? (Sin / B) : 31;
    if (V <= 0) V = 1;

    if (B % 4 == 0) {
        const int n4 = (int)(B / 4);
        int blocks = NSM * CTAS_PER_SM;
        const int maxb = (n4 + THREADS - 1) / THREADS;
        if (blocks > maxb) blocks = maxb;
        if (V == 31) {
            vote_vec4_persist<31><<<blocks, THREADS>>>(
                (const uint4*)in, (float4*)out, n4);
        } else {
            vote_vec4_dyn<<<blocks, THREADS>>>(
                (const uint4*)in, (float4*)out, n4, (int)V);
        }
    } else {
        int blocks = (int)((B + THREADS - 1) / THREADS);
        if (blocks > NSM * 32) blocks = NSM * 32;
        vote_scalar<<<blocks, THREADS>>>(in, out, (int)B, (int)V);
    }
}

// round 7
// speedup vs baseline: 1.0483x; 1.0429x over previous
#include <cuda_runtime.h>
#include <cuda_bf16.h>
#include <cstdint>

// HardBinaryVote: inputs [V=31, B=2,000,000] row-major {0,1} (int32 or f32 —
// either way vote == (bits != 0)); out[b] (FLOAT32) = majority = (2*ones > V).
//
// R7: exact one-shot partition (1 uint4 per thread, zero per-thread imbalance),
// regs capped to 32 via __launch_bounds__(256,8) for true 8 CTAs/SM, streaming
// .cs loads/stores, dual accumulation chains. Model: irreducible 256 MB at the
// measured ~6.1 TB/s pattern ceiling -> ~42 us kernel.

static constexpr int THREADS = 256;

template <int V>
__global__ __launch_bounds__(THREADS, 8)
void vote_vec4_oneshot(const uint4* __restrict__ in4,
                       float4* __restrict__ out4,
                       int n4) {
    const int idx = blockIdx.x * THREADS + threadIdx.x;
    if (idx >= n4) return;

    // Two independent accumulation chains per component.
    int a0 = 0, a1 = 0, a2 = 0, a3 = 0;
    int b0 = 0, b1 = 0, b2 = 0, b3 = 0;
    const uint4* __restrict__ p = in4 + idx;

#pragma unroll
    for (int v = 0; v < V; v += 2) {
        uint4 x = __ldcs(&p[(long long)v * n4]);
        a0 += (x.x != 0u); a1 += (x.y != 0u);
        a2 += (x.z != 0u); a3 += (x.w != 0u);
        if (v + 1 < V) {
            uint4 y = __ldcs(&p[(long long)(v + 1) * n4]);
            b0 += (y.x != 0u); b1 += (y.y != 0u);
            b2 += (y.z != 0u); b3 += (y.w != 0u);
        }
    }

    const int s0 = a0 + b0, s1 = a1 + b1, s2 = a2 + b2, s3 = a3 + b3;
    float4 o;
    o.x = (2 * s0 > V) ? 1.0f : 0.0f;
    o.y = (2 * s1 > V) ? 1.0f : 0.0f;
    o.z = (2 * s2 > V) ? 1.0f : 0.0f;
    o.w = (2 * s3 > V) ? 1.0f : 0.0f;
    __stcs(&out4[idx], o);
}

// Runtime-V vectorized fallback.
__global__ __launch_bounds__(THREADS)
void vote_vec4_dyn(const uint4* __restrict__ in4,
                   float4* __restrict__ out4,
                   int n4, int V) {
    const int idx = blockIdx.x * THREADS + threadIdx.x;
    if (idx >= n4) return;
    int s0 = 0, s1 = 0, s2 = 0, s3 = 0;
#pragma unroll 8
    for (int v = 0; v < V; v++) {
        uint4 x = __ldcs(&in4[(long long)v * n4 + idx]);
        s0 += (x.x != 0u); s1 += (x.y != 0u);
        s2 += (x.z != 0u); s3 += (x.w != 0u);
    }
    float4 o;
    o.x = (2 * s0 > V) ? 1.0f : 0.0f;
    o.y = (2 * s1 > V) ? 1.0f : 0.0f;
    o.z = (2 * s2 > V) ? 1.0f : 0.0f;
    o.w = (2 * s3 > V) ? 1.0f : 0.0f;
    __stcs(&out4[idx], o);
}

// Scalar fallback for B % 4 != 0.
__global__ __launch_bounds__(THREADS)
void vote_scalar(const unsigned int* __restrict__ in,
                 float* __restrict__ out,
                 int B, int V) {
    int b = blockIdx.x * THREADS + threadIdx.x;
    const int stride = gridDim.x * THREADS;
    for (; b < B; b += stride) {
        int s = 0;
        for (int v = 0; v < V; v++) s += (in[(long long)v * B + b] != 0u);
        out[b] = (2 * s > V) ? 1.0f : 0.0f;
    }
}

extern "C" void kernel_launch(void* const* d_in, const int* in_sizes, int n_in,
                              void* d_out, int out_size) {
    const unsigned int* in = (const unsigned int*)d_in[0];
    float* out = (float*)d_out;

    const long long Sin = in_sizes[0];
    long long B = out_size;
    if (B <= 0) return;
    long long V = (Sin % B == 0) ? (Sin / B) : 31;
    if (V <= 0) V = 1;

    if (B % 4 == 0) {
        const int n4 = (int)(B / 4);
        const int blocks = (n4 + THREADS - 1) / THREADS;
        if (V == 31) {
            vote_vec4_oneshot<31><<<blocks, THREADS>>>(
                (const uint4*)in, (float4*)out, n4);
        } else {
            vote_vec4_dyn<<<blocks, THREADS>>>(
                (const uint4*)in, (float4*)out, n4, (int)V);
        }
    } else {
        int blocks = (int)((B + THREADS - 1) / THREADS);
        if (blocks > 148 * 32) blocks = 148 * 32;
        vote_scalar<<<blocks, THREADS>>>(in, out, (int)B, (int)V);
    }
}